// round 13
// baseline (speedup 1.0000x reference)
#include <cuda_runtime.h>
#include <cstdint>

// Problem constants
#define NF 8
#define NK 16
#define NY 16
#define NX 16
#define NP 32
#define NT 8
#define NB 64
#define VOL 65536          // elements per (b,f)

#define AS_STRIDE 68       // 64 cols + 4 pad (conflict-free writes / LDS.32)
#define BS_STRIDE 24       // 16 cols + 8 pad (conflict-free b-frag LDS.32)
#define AS_U32    (64*AS_STRIDE)                 // per buffer (fp32 words)
#define AS_BYTES  (2*AS_U32*4)                   // 34816 (double buffer)
#define BS_BYTES  (256*BS_STRIDE*4)              // 24576
#define SP_BYTES  (4*16*16*4)                    // 4096
#define SMEM_TOTAL (AS_BYTES + BS_BYTES + SP_BYTES)   // 63488 -> 3 CTAs/SM

#define NCTA 2048

// Device globals (no allocation allowed). All zero at module load; the
// finalize step re-zeroes them each launch so graph replays are identical.
__device__ float        g_unnorm[NB*NF*NK];   // unnormalized features
__device__ float        g_integ[NF*NK];       // integration sums
__device__ unsigned int g_done;               // completed-CTA ticket counter

__device__ __forceinline__ uint32_t f2tf32(float x) {
    uint32_t r; asm("cvt.rna.tf32.f32 %0, %1;" : "=r"(r) : "f"(x)); return r;
}
__device__ __forceinline__ void mma_tf32(float c[4], uint32_t a0, uint32_t a1,
                                         uint32_t a2, uint32_t a3,
                                         uint32_t b0, uint32_t b1) {
    asm volatile(
        "mma.sync.aligned.m16n8k8.row.col.f32.tf32.tf32.f32 "
        "{%0,%1,%2,%3},{%4,%5,%6,%7},{%8,%9},{%0,%1,%2,%3};"
        : "+f"(c[0]), "+f"(c[1]), "+f"(c[2]), "+f"(c[3])
        : "r"(a0), "r"(a1), "r"(a2), "r"(a3), "r"(b0), "r"(b1));
}

// cp.async helpers (16B, default .ca path)
__device__ __forceinline__ void cp16(void* dst_smem, const void* src) {
    uint32_t d = (uint32_t)__cvta_generic_to_shared(dst_smem);
    asm volatile("cp.async.ca.shared.global [%0],[%1],16;" :: "r"(d), "l"(src));
}
__device__ __forceinline__ void cp_commit() {
    asm volatile("cp.async.commit_group;");
}
template<int N> __device__ __forceinline__ void cp_wait() {
    asm volatile("cp.async.wait_group %0;" :: "n"(N));
}

__device__ __forceinline__ int bitrev4(int l) {
    return ((l & 1) << 3) | ((l & 2) << 1) | ((l & 4) >> 1) | ((l & 8) >> 3);
}

// ---------------------------------------------------------------------------
// Single fused kernel: grid = 2048 (f = bid&7, sl = bid>>3 = one yx slice).
// C[64,16] = patch[64, 256] x W[256, 16] (tf32 mma.sync m16n8k8).
// Per CTA: builds its own 1D kernel tables (hidden under cp.async stage-0
// latency), builds unnormalized W in smem, reduces W into g_integ (16-shfl
// halving transpose), runs the R12 cp.async double-buffered GEMM mainloop,
// and atomically accumulates unnormalized partials into g_unnorm.
// The LAST CTA to finish (ticket counter) normalizes into out and re-zeroes
// all device-global state for graph-replay determinism.
// ---------------------------------------------------------------------------
__global__ __launch_bounds__(256, 3)
void feat_kernel(const float* __restrict__ patch, const float* __restrict__ qw,
                 const float* __restrict__ mu_lat, const float* __restrict__ ls_lat,
                 const float* __restrict__ mu_lon, const float* __restrict__ ls_lon,
                 const float* __restrict__ mu_lev, const float* __restrict__ ls_lev,
                 const float* __restrict__ lt_time,
                 float* __restrict__ out)
{
    extern __shared__ __align__(16) char dynsmem[];
    float*    As    = (float*)dynsmem;                         // [2][64][68] fp32
    uint32_t* Bs    = (uint32_t*)(dynsmem + AS_BYTES);         // [256][24] tf32
    float*    s_par = (float*)(dynsmem + AS_BYTES + BS_BYTES); // [4][16][16]
    __shared__ float s_cl[16];            // klat*klon per k (unnormalized)
    __shared__ float s_r[16];             // geometric ratio per k
    __shared__ float s_klev[16][33];      // klev[k][p] (padded)
    __shared__ float s_ired[8*16];        // per-warp integ partials
    __shared__ int   s_last;

    const int bid  = blockIdx.x;
    const int f    = bid & 7;
    const int sl   = bid >> 3;            // yx index 0..255
    const int tid  = threadIdx.x;
    const int lane = tid & 31, wid = tid >> 5;
    const int g = lane >> 2, tg = lane & 3;
    const int mt = wid & 3, kh = wid >> 2;

    const size_t bstride = (size_t)NF * VOL;
    const float* abase = patch + (size_t)f * VOL + (size_t)sl * 256;
    const int row0 = tid >> 4;            // rows row0, +16, +32, +48
    const int c4   = tid & 15;

    // Kick off stage 0 copies immediately (overlap with table build)
    #pragma unroll
    for (int it = 0; it < 4; ++it)
        cp16(&As[(row0 + it*16)*AS_STRIDE + c4*4],
             abase + (size_t)(row0 + it*16) * bstride + c4*4);
    cp_commit();

    // ---- In-CTA table build (replaces the prep kernel) ----
    if (tid < 16) {
        const int fk = f*16 + tid;
        const float cy = -1.f + 2.f * (float)(sl >> 4) / (float)(NY - 1);
        const float zy = (cy - mu_lat[fk]) / expf(ls_lat[fk]);
        const float cx = -1.f + 2.f * (float)(sl & 15) / (float)(NX - 1);
        const float zx = (cx - mu_lon[fk]) / expf(ls_lon[fk]);
        s_cl[tid] = expf(-0.5f * zy * zy) * expf(-0.5f * zx * zx);
        s_r[tid]  = expf(-1.f / (expf(lt_time[fk]) + 1e-6f));
    }
    {   // klev: 512 values, 2 per thread
        const int k  = tid >> 4;
        const int p0 = tid & 15;
        const int fk = f*16 + k;
        const float mu = mu_lev[fk];
        const float si = expf(ls_lev[fk]);
        #pragma unroll
        for (int h = 0; h < 2; ++h) {
            const int p = p0 + h*16;
            const float c = -1.f + 2.f * (float)p / (float)(NP - 1);
            const float z = (c - mu) / si;
            s_klev[k][p] = expf(-0.5f * z * z);
        }
    }
    __syncthreads();

    // ---- Build unnormalized W (tf32 into Bs + float copy for integ) ----
    float wf[16];
    {
        const int p = (tid >> 3) & 31, t = tid & 7;
        const float qwv = qw[sl*256 + tid];
        #pragma unroll
        for (int kq = 0; kq < 4; ++kq) {
            uint4 pk;
            uint32_t* pe = (uint32_t*)&pk;
            #pragma unroll
            for (int e = 0; e < 4; ++e) {
                const int k = kq*4 + e;
                const float r = s_r[k];
                const float r2 = r*r, r4 = r2*r2;
                float rt = 1.f;
                if (t & 1) rt *= r;
                if (t & 2) rt *= r2;
                if (t & 4) rt *= r4;
                const float val = qwv * s_klev[k][p] * rt * s_cl[k];
                wf[k] = val;
                pe[e] = f2tf32(val);
            }
            *(uint4*)&Bs[tid*BS_STRIDE + kq*4] = pk;
        }
    }

    // Stage 1 copies into buffer 1
    #pragma unroll
    for (int it = 0; it < 4; ++it)
        cp16(&As[AS_U32 + (row0 + it*16)*AS_STRIDE + c4*4],
             abase + (size_t)(row0 + it*16) * bstride + 64 + c4*4);
    cp_commit();

    // ---- integ partial: reduce wf over 256 threads (16 values) ----
    {
        #pragma unroll
        for (int s = 0; s < 4; ++s) {
            const int stride = 1 << s;
            const int nh = 8 >> s;
            const bool hi = (lane >> s) & 1;
            #pragma unroll
            for (int i = 0; i < nh; ++i) {
                float send = hi ? wf[i] : wf[i + nh];
                float keep = hi ? wf[i + nh] : wf[i];
                wf[i] = keep + __shfl_xor_sync(0xffffffffu, send, stride);
            }
        }
        wf[0] += __shfl_xor_sync(0xffffffffu, wf[0], 16);
        if (lane < 16) s_ired[wid*16 + bitrev4(lane)] = wf[0];
    }
    __syncthreads();
    if (tid < 16) {
        float s = 0.f;
        #pragma unroll
        for (int w8 = 0; w8 < 8; ++w8) s += s_ired[w8*16 + tid];
        atomicAdd(&g_integ[f*16 + tid], s);
    }

    // ---- Mainloop (identical to R12) ----
    float acc[2][4] = {};
    #pragma unroll
    for (int sub = 0; sub < 4; ++sub) {
        if (sub < 3) cp_wait<1>(); else cp_wait<0>();
        __syncthreads();

        const float* Ab = As + (sub & 1)*AS_U32;
        const float* ar0 = Ab + (mt*16 + g    )*AS_STRIDE;
        const float* ar8 = Ab + (mt*16 + g + 8)*AS_STRIDE;
        #pragma unroll
        for (int j = 0; j < 4; ++j) {
            const int icl = kh*32 + j*8;       // col within 64-col round
            const int icb = sub*64 + icl;      // row in Bs (0..255)
            const uint32_t a0 = f2tf32(ar0[icl + tg]);
            const uint32_t a1 = f2tf32(ar8[icl + tg]);
            const uint32_t a2 = f2tf32(ar0[icl + tg + 4]);
            const uint32_t a3 = f2tf32(ar8[icl + tg + 4]);
            const uint32_t b0 = Bs[(icb + tg    )*BS_STRIDE + g];
            const uint32_t b1 = Bs[(icb + tg + 4)*BS_STRIDE + g];
            const uint32_t c0 = Bs[(icb + tg    )*BS_STRIDE + g + 8];
            const uint32_t c1 = Bs[(icb + tg + 4)*BS_STRIDE + g + 8];
            mma_tf32(acc[0], a0, a1, a2, a3, b0, b1);
            mma_tf32(acc[1], a0, a1, a2, a3, c0, c1);
        }
        __syncthreads();   // buffer sub&1 fully consumed

        if (sub < 2) {
            const int col0 = (sub + 2)*64;
            #pragma unroll
            for (int it = 0; it < 4; ++it)
                cp16(&As[(sub & 1)*AS_U32 + (row0 + it*16)*AS_STRIDE + c4*4],
                     abase + (size_t)(row0 + it*16) * bstride + col0 + c4*4);
            cp_commit();
        }
    }

    // ---- Epilogue: pair-reduce K-halves, atomicAdd into g_unnorm ----
    if (kh == 1) {
        float* sp = s_par + mt*256;
        sp[(g    )*16 + tg*2    ] = acc[0][0];
        sp[(g    )*16 + tg*2 + 1] = acc[0][1];
        sp[(g + 8)*16 + tg*2    ] = acc[0][2];
        sp[(g + 8)*16 + tg*2 + 1] = acc[0][3];
        sp[(g    )*16 + 8 + tg*2    ] = acc[1][0];
        sp[(g    )*16 + 8 + tg*2 + 1] = acc[1][1];
        sp[(g + 8)*16 + 8 + tg*2    ] = acc[1][2];
        sp[(g + 8)*16 + 8 + tg*2 + 1] = acc[1][3];
    }
    __syncthreads();
    if (kh == 0) {
        const float* sp = s_par + mt*256;
        const int r0 = mt*16 + g, r1 = r0 + 8;
        float* o0 = g_unnorm + (size_t)r0 * (NF*NK) + f*NK;
        float* o1 = g_unnorm + (size_t)r1 * (NF*NK) + f*NK;
        atomicAdd(&o0[tg*2    ], acc[0][0] + sp[(g    )*16 + tg*2    ]);
        atomicAdd(&o0[tg*2 + 1], acc[0][1] + sp[(g    )*16 + tg*2 + 1]);
        atomicAdd(&o1[tg*2    ], acc[0][2] + sp[(g + 8)*16 + tg*2    ]);
        atomicAdd(&o1[tg*2 + 1], acc[0][3] + sp[(g + 8)*16 + tg*2 + 1]);
        atomicAdd(&o0[8 + tg*2    ], acc[1][0] + sp[(g    )*16 + 8 + tg*2    ]);
        atomicAdd(&o0[8 + tg*2 + 1], acc[1][1] + sp[(g    )*16 + 8 + tg*2 + 1]);
        atomicAdd(&o1[8 + tg*2    ], acc[1][2] + sp[(g + 8)*16 + 8 + tg*2    ]);
        atomicAdd(&o1[8 + tg*2 + 1], acc[1][3] + sp[(g + 8)*16 + 8 + tg*2 + 1]);
    }

    // ---- Completion ticket; last CTA normalizes + resets state ----
    __syncthreads();
    __threadfence();
    if (tid == 0) {
        unsigned int ticket = atomicAdd(&g_done, 1u);
        s_last = (ticket == NCTA - 1) ? 1 : 0;
    }
    __syncthreads();
    if (s_last) {
        __threadfence();   // acquire: all other CTAs' atomics visible
        #pragma unroll
        for (int it = 0; it < 4; ++it) {
            const int o = it*2048 + tid*8;    // 8 consecutive floats
            float4 u0 = *(float4*)&g_unnorm[o];
            float4 u1 = *(float4*)&g_unnorm[o + 4];
            const int fk = o & 127;           // o%8==0 -> fk..fk+7 within row
            float4 r0, r1;
            r0.x = u0.x / (g_integ[fk    ] + 1e-4f);
            r0.y = u0.y / (g_integ[fk + 1] + 1e-4f);
            r0.z = u0.z / (g_integ[fk + 2] + 1e-4f);
            r0.w = u0.w / (g_integ[fk + 3] + 1e-4f);
            r1.x = u1.x / (g_integ[fk + 4] + 1e-4f);
            r1.y = u1.y / (g_integ[fk + 5] + 1e-4f);
            r1.z = u1.z / (g_integ[fk + 6] + 1e-4f);
            r1.w = u1.w / (g_integ[fk + 7] + 1e-4f);
            *(float4*)&out[o]     = r0;
            *(float4*)&out[o + 4] = r1;
        }
        __syncthreads();   // all reads of g_integ/g_unnorm done
        #pragma unroll
        for (int it = 0; it < 4; ++it) {
            const int o = it*2048 + tid*8;
            *(float4*)&g_unnorm[o]     = make_float4(0.f, 0.f, 0.f, 0.f);
            *(float4*)&g_unnorm[o + 4] = make_float4(0.f, 0.f, 0.f, 0.f);
        }
        if (tid < 128) g_integ[tid] = 0.f;
        if (tid == 0) g_done = 0u;
    }
}

// ---------------------------------------------------------------------------
// Launch. Inputs (metadata order): patch, quadweights, mu_lat, logsigma_lat,
// mu_lon, logsigma_lon, mu_lev, logsigma_lev, logtau_time.
// Single fused kernel launch.
// ---------------------------------------------------------------------------
extern "C" void kernel_launch(void* const* d_in, const int* in_sizes, int n_in,
                              void* d_out, int out_size)
{
    (void)in_sizes; (void)n_in; (void)out_size;
    const float* patch  = (const float*)d_in[0];
    const float* qw     = (const float*)d_in[1];
    const float* mu_lat = (const float*)d_in[2];
    const float* ls_lat = (const float*)d_in[3];
    const float* mu_lon = (const float*)d_in[4];
    const float* ls_lon = (const float*)d_in[5];
    const float* mu_lev = (const float*)d_in[6];
    const float* ls_lev = (const float*)d_in[7];
    const float* lt     = (const float*)d_in[8];
    float* out = (float*)d_out;

    static bool attr_set = false;
    if (!attr_set) {
        cudaFuncSetAttribute(feat_kernel,
                             cudaFuncAttributeMaxDynamicSharedMemorySize, SMEM_TOTAL);
        attr_set = true;
    }

    feat_kernel<<<NCTA, 256, SMEM_TOTAL>>>(patch, qw, mu_lat, ls_lat,
                                           mu_lon, ls_lon, mu_lev, ls_lev,
                                           lt, out);
}